// round 8
// baseline (speedup 1.0000x reference)
#include <cuda_runtime.h>
#include <cuda_bf16.h>
#include <float.h>
#include <stdint.h>

#define NQ    65536
#define NE    4096
#define ED    256
#define CAND  64
#define W_MARGIN 1.0e-3f

#define QB     256          // queries per CTA (screen)
#define TN     64           // codes per tile
#define NTILES (NE / TN)    // 64

// Scratch (no allocations allowed)
__device__ float g_A[NQ];
__device__ float g_B[NE];
__device__ int   g_cnt[NQ];
__device__ int   g_cand[NQ * CAND];
__device__ __nv_bfloat16 g_cbbf[NE * ED];   // bf16 codebook (2MB, L2-resident)

// ---------------------------------------------------------------------------
// helpers (base-ISA only: harness PTX target is sm_103 base — no tcgen05)
// ---------------------------------------------------------------------------
__device__ __forceinline__ uint32_t smem_u32(const void* p) {
    uint32_t a;
    asm("{ .reg .u64 t; cvta.to.shared.u64 t, %1; cvt.u32.u64 %0, t; }"
        : "=r"(a) : "l"(p));
    return a;
}
__device__ __forceinline__ void mbar_init(uint32_t a, uint32_t n) {
    asm volatile("mbarrier.init.shared.b64 [%0], %1;" :: "r"(a), "r"(n) : "memory");
}
__device__ __forceinline__ void mbar_arrive(uint32_t a) {
    asm volatile("mbarrier.arrive.shared.b64 _, [%0];" :: "r"(a) : "memory");
}
__device__ __forceinline__ void mbar_wait(uint32_t a, uint32_t ph) {
    uint32_t done;
    asm volatile("{\n\t.reg .pred p;\n\t"
                 "mbarrier.try_wait.parity.acquire.cta.shared::cta.b64 p, [%1], %2;\n\t"
                 "selp.b32 %0,1,0,p;\n\t}"
                 : "=r"(done) : "r"(a), "r"(ph) : "memory");
    if (!done) {
        asm volatile("{\n\t.reg .pred P1;\n\t"
                     "WL_%=:\n\t"
                     "mbarrier.try_wait.parity.acquire.cta.shared::cta.b64 P1, [%0], %1, 0x989680;\n\t"
                     "@P1 bra.uni WD_%=;\n\t"
                     "bra.uni WL_%=;\n\t"
                     "WD_%=:\n\t}"
                     :: "r"(a), "r"(ph) : "memory");
    }
}
__device__ __forceinline__ void cp16(uint32_t dst, const void* src) {
    asm volatile("cp.async.ca.shared.global [%0], [%1], 16;"
                 :: "r"(dst), "l"(src) : "memory");
}
// pack two f32 -> bf16x2 (rne): lo in low half, hi in high half
__device__ __forceinline__ uint32_t pk2(float lo, float hi) {
    uint32_t r;
    asm("cvt.rn.bf16x2.f32 %0, %1, %2;" : "=r"(r) : "f"(hi), "f"(lo));
    return r;
}
__device__ __forceinline__ void ldsm4(uint32_t r[4], uint32_t addr) {
    asm volatile("ldmatrix.sync.aligned.m8n8.x4.shared.b16 {%0,%1,%2,%3}, [%4];"
                 : "=r"(r[0]), "=r"(r[1]), "=r"(r[2]), "=r"(r[3]) : "r"(addr));
}
__device__ __forceinline__ void mma_bf16(float c[4], const uint32_t a[4],
                                         uint32_t b0, uint32_t b1) {
    asm volatile("mma.sync.aligned.m16n8k16.row.col.f32.bf16.bf16.f32 "
                 "{%0,%1,%2,%3}, {%4,%5,%6,%7}, {%8,%9}, {%0,%1,%2,%3};"
                 : "+f"(c[0]), "+f"(c[1]), "+f"(c[2]), "+f"(c[3])
                 : "r"(a[0]), "r"(a[1]), "r"(a[2]), "r"(a[3]), "r"(b0), "r"(b1));
}

// ---------------------------------------------------------------------------
// Row sums of squares — bit-exact reference order: fadd(fmul), sequential.
// ---------------------------------------------------------------------------
__global__ void rowsq_z(const float4* __restrict__ z4) {
    int n = blockIdx.x * blockDim.x + threadIdx.x;
    if (n >= NQ) return;
    const float4* p = z4 + (size_t)n * (ED / 4);
    float acc = 0.0f;
    #pragma unroll 8
    for (int i = 0; i < ED / 4; i++) {
        float4 v = __ldg(p + i);
        acc = __fadd_rn(acc, __fmul_rn(v.x, v.x));
        acc = __fadd_rn(acc, __fmul_rn(v.y, v.y));
        acc = __fadd_rn(acc, __fmul_rn(v.z, v.z));
        acc = __fadd_rn(acc, __fmul_rn(v.w, v.w));
    }
    g_A[n] = acc;
}

__global__ void rowsq_cb(const float4* __restrict__ c4) {
    int n = blockIdx.x * blockDim.x + threadIdx.x;
    if (n >= NE) return;
    const float4* p = c4 + (size_t)n * (ED / 4);
    float acc = 0.0f;
    #pragma unroll 8
    for (int i = 0; i < ED / 4; i++) {
        float4 v = __ldg(p + i);
        acc = __fadd_rn(acc, __fmul_rn(v.x, v.x));
        acc = __fadd_rn(acc, __fmul_rn(v.y, v.y));
        acc = __fadd_rn(acc, __fmul_rn(v.z, v.z));
        acc = __fadd_rn(acc, __fmul_rn(v.w, v.w));
    }
    g_B[n] = acc;
}

// Codebook f32 -> bf16 (rne), natural element order, coalesced.
__global__ void cvt_cb(const float4* __restrict__ c4) {
    int t = blockIdx.x * 256 + threadIdx.x;   // NE*ED/8 = 131072
    if (t >= NE * ED / 8) return;
    float4 v0 = __ldg(c4 + 2 * t);
    float4 v1 = __ldg(c4 + 2 * t + 1);
    uint4 o;
    o.x = pk2(v0.x, v0.y); o.y = pk2(v0.z, v0.w);
    o.z = pk2(v1.x, v1.y); o.w = pk2(v1.z, v1.w);
    ((uint4*)g_cbbf)[t] = o;
}

// ---------------------------------------------------------------------------
// Phase 1: bf16 mma.sync screening, warp-specialized.
// CTA = 256 queries (A bf16 persistent in smem). 8 consumer warps (32q x 64c
// each); 1 producer warp cp.asyncs the pre-converted bf16 B tile + row-sumsq
// through a 2-deep mbarrier ring. Collects codes with s <= runmin + W.
// ---------------------------------------------------------------------------
#define SA_OFF   0
#define SB_OFF   131072
#define BSQ_OFF  196608
#define CNT_OFF  197120
#define MB_OFF   198144
#define SCREEN_SMEM (198176 + 1024)

__global__ void __launch_bounds__(288, 1)
vq_screen(const float* __restrict__ z, const float* __restrict__ cb) {
    extern __shared__ char smraw[];
    char* smem = (char*)(((uintptr_t)smraw + 1023) & ~(uintptr_t)1023);
    const uint32_t smb = smem_u32(smem);

    const int tid  = threadIdx.x;
    const int lane = tid & 31;
    const int w    = tid >> 5;           // 0..8
    const int q0   = blockIdx.x * QB;

    float* bsq = (float*)(smem + BSQ_OFF);
    int*   cnt = (int*)(smem + CNT_OFF);
    const uint32_t mb = smb + MB_OFF;    // +0/+8 full[2], +16/+24 empty[2]

    const float4* z4 = (const float4*)z;

    if (tid == 0) {
        mbar_init(mb + 0, 32);  mbar_init(mb + 8, 32);    // full: producer warp
        mbar_init(mb + 16, 256); mbar_init(mb + 24, 256); // empty: consumers
    }
    if (tid < 256) cnt[tid] = 0;

    // ---- stage A: f32 -> bf16 (rne), rows of 512B, 16B-unit XOR swizzle ----
    for (int e = tid; e < QB * 32; e += 288) {
        int q = e >> 5, c = e & 31;
        float4 v0 = __ldg(z4 + (size_t)(q0 + q) * 64 + 2 * c);
        float4 v1 = __ldg(z4 + (size_t)(q0 + q) * 64 + 2 * c + 1);
        uint4 t;
        t.x = pk2(v0.x, v0.y); t.y = pk2(v0.z, v0.w);
        t.z = pk2(v1.x, v1.y); t.w = pk2(v1.z, v1.w);
        *(uint4*)(smem + SA_OFF + q * 512 + ((c ^ (q & 7)) << 4)) = t;
    }
    __syncthreads();

    if (w == 8) {
        // ---------------- producer warp: pure cp.async staging ----------------
        const char* src = (const char*)g_cbbf;
        for (int nt = 0; nt < NTILES; nt++) {
            const int b = nt & 1;
            if (nt >= 2) mbar_wait(mb + 16 + b * 8, ((nt - 2) >> 1) & 1);
            const uint32_t bp = smb + SB_OFF + b * 32768;
            const size_t gs = (size_t)nt * TN * 512;   // bytes (bf16 rows=512B)
            #pragma unroll 8
            for (int r = 0; r < TN; r++)
                cp16(bp + r * 512 + (((uint32_t)(lane ^ (r & 7))) << 4),
                     src + gs + r * 512 + lane * 16);
            if (lane < 16)
                cp16(smb + BSQ_OFF + b * 256 + lane * 16,
                     (const char*)g_B + (size_t)nt * 256 + lane * 16);
            asm volatile("cp.async.commit_group;" ::: "memory");
            if (nt >= 1) {
                asm volatile("cp.async.wait_group 1;" ::: "memory");
                mbar_arrive(mb + ((nt - 1) & 1) * 8);
            }
        }
        asm volatile("cp.async.wait_group 0;" ::: "memory");
        mbar_arrive(mb + ((NTILES - 1) & 1) * 8);
    } else {
        // ---------------- consumers (warps 0-7): 32q x 64c each ----------------
        float Aq[4], runmin[4];
        int qloc[4];
        #pragma unroll
        for (int i = 0; i < 4; i++) {
            qloc[i] = w * 32 + i * 8 + (lane >> 2);
            Aq[i] = g_A[q0 + qloc[i]];
            runmin[i] = FLT_MAX;
        }

        for (int nt = 0; nt < NTILES; nt++) {
            const int b = nt & 1;
            mbar_wait(mb + b * 8, (nt >> 1) & 1);

            float acc[2][8][4];
            #pragma unroll
            for (int mi = 0; mi < 2; mi++)
                #pragma unroll
                for (int j = 0; j < 8; j++)
                    #pragma unroll
                    for (int p = 0; p < 4; p++) acc[mi][j][p] = 0.0f;

            const uint32_t sb_base = smb + SB_OFF + b * 32768;
            #pragma unroll
            for (int kc = 0; kc < 16; kc++) {
                uint32_t a[2][4];
                #pragma unroll
                for (int mi = 0; mi < 2; mi++) {
                    int qr = w * 32 + mi * 16 + (lane & 15);
                    uint32_t ad = smb + SA_OFF + qr * 512 +
                        ((((kc << 1) | (lane >> 4)) ^ (qr & 7)) << 4);
                    ldsm4(a[mi], ad);
                }
                uint32_t bf[4][4];
                #pragma unroll
                for (int jp = 0; jp < 4; jp++) {
                    int nr = jp * 16 + (lane & 7) + ((lane & 16) >> 1);
                    int cc = (kc << 1) | ((lane >> 3) & 1);
                    uint32_t ad = sb_base + nr * 512 + ((cc ^ (nr & 7)) << 4);
                    ldsm4(bf[jp], ad);
                }
                #pragma unroll
                for (int mi = 0; mi < 2; mi++)
                    #pragma unroll
                    for (int jp = 0; jp < 4; jp++) {
                        mma_bf16(acc[mi][jp * 2],     a[mi], bf[jp][0], bf[jp][1]);
                        mma_bf16(acc[mi][jp * 2 + 1], a[mi], bf[jp][2], bf[jp][3]);
                    }
            }

            float Bn[16];
            #pragma unroll
            for (int j = 0; j < 8; j++) {
                Bn[2 * j]     = bsq[b * 64 + j * 8 + (lane & 3) * 2];
                Bn[2 * j + 1] = bsq[b * 64 + j * 8 + (lane & 3) * 2 + 1];
            }
            mbar_arrive(mb + 16 + b * 8);

            const int n0t = nt * TN;
            float thr[4];
            #pragma unroll
            for (int i = 0; i < 4; i++) {
                const int mi = i >> 1, rh = i & 1;
                float m = FLT_MAX;
                #pragma unroll
                for (int j = 0; j < 8; j++) {
                    float v0 = fmaf(-2.0f, acc[mi][j][rh * 2],     Aq[i] + Bn[2 * j]);
                    float v1 = fmaf(-2.0f, acc[mi][j][rh * 2 + 1], Aq[i] + Bn[2 * j + 1]);
                    m = fminf(m, fminf(v0, v1));
                }
                m = fminf(m, __shfl_xor_sync(~0u, m, 1));
                m = fminf(m, __shfl_xor_sync(~0u, m, 2));
                runmin[i] = fminf(runmin[i], m);
                thr[i] = runmin[i] + W_MARGIN;
            }
            #pragma unroll
            for (int i = 0; i < 4; i++) {
                const int mi = i >> 1, rh = i & 1;
                #pragma unroll
                for (int j = 0; j < 8; j++) {
                    #pragma unroll
                    for (int p = 0; p < 2; p++) {
                        float v = fmaf(-2.0f, acc[mi][j][rh * 2 + p],
                                       Aq[i] + Bn[2 * j + p]);
                        if (v <= thr[i]) {
                            int sl = atomicAdd(&cnt[qloc[i]], 1);
                            if (sl < CAND)
                                g_cand[(size_t)(q0 + qloc[i]) * CAND + sl] =
                                    n0t + j * 8 + (lane & 3) * 2 + p;
                        }
                    }
                }
            }
        }
    }

    __syncthreads();
    if (tid < 256) g_cnt[q0 + tid] = cnt[tid];
}

// ---------------------------------------------------------------------------
// Phase 2: exact verification, 64 queries per block. z rows staged in smem
// (padded, conflict-free); (q,cand) pairs flattened into a work queue so all
// lanes stay busy; winner = packed-u64 atomicMin (d>0 => float bits monotone;
// low word = idx => exact first-index tie-break). Overflow -> full scan.
// ---------------------------------------------------------------------------
#define EX_Q 64
#define XS_Z    0                    // 64 rows x 65 float4 = 66560B
#define XS_PAIR 66560                // 4096 x u32 = 16384
#define XS_BEST 82944                // 64 x u64 = 512
#define XS_A    83456                // 64 x f32
#define XS_CNT  83712                // 64 x i32
#define XS_PREF 83968                // 65 x i32 (+pad)
#define XS_OVF  84240                // 64 x i32
#define XS_WIDX 84496                // 64 x i32
#define EXACT_SMEM 84752

__global__ void __launch_bounds__(256, 2)
vq_exact(const float* __restrict__ z, const float* __restrict__ cb,
         float* __restrict__ out) {
    extern __shared__ char sm[];
    float4*             zs    = (float4*)(sm + XS_Z);
    uint32_t*           pairs = (uint32_t*)(sm + XS_PAIR);
    unsigned long long* best  = (unsigned long long*)(sm + XS_BEST);
    float*              sA    = (float*)(sm + XS_A);
    int*                scnt  = (int*)(sm + XS_CNT);
    int*                spref = (int*)(sm + XS_PREF);
    int*                sovf  = (int*)(sm + XS_OVF);
    int*                widx  = (int*)(sm + XS_WIDX);

    const int tid = threadIdx.x;
    const int q0  = blockIdx.x * EX_Q;

    const float4* z4  = (const float4*)z;
    const float4* cb4 = (const float4*)cb;

    if (tid < EX_Q) {
        int c = g_cnt[q0 + tid];
        int ov = (c > CAND);
        sovf[tid] = ov;
        scnt[tid] = ov ? 0 : c;
        sA[tid]   = g_A[q0 + tid];
        best[tid] = 0xFFFFFFFFFFFFFFFFull;
    }
    for (int e = tid; e < EX_Q * 64; e += 256) {
        int r = e >> 6, f = e & 63;
        zs[r * 65 + f] = __ldg(z4 + (size_t)(q0 + r) * 64 + f);
    }
    __syncthreads();
    if (tid == 0) {
        int run = 0;
        for (int i = 0; i < EX_Q; i++) { spref[i] = run; run += scnt[i]; }
        spref[EX_Q] = run;
    }
    __syncthreads();
    if (tid < EX_Q) {
        int p0 = spref[tid], n = scnt[tid];
        for (int j = 0; j < n; j++)
            pairs[p0 + j] = ((uint32_t)tid << 12)
                          | (uint32_t)g_cand[(size_t)(q0 + tid) * CAND + j];
    }
    __syncthreads();

    const int total = spref[EX_Q];
    for (int p = tid; p < total; p += 256) {
        uint32_t pr = pairs[p];
        int q = pr >> 12, cdx = pr & 4095;
        const float4* crow = cb4 + (size_t)cdx * 64;
        const float4* zr = zs + q * 65;
        float dot = 0.0f;
        #pragma unroll 8
        for (int f = 0; f < 64; f++) {
            float4 zv = zr[f];
            float4 cv = __ldg(crow + f);
            dot = fmaf(zv.x, cv.x, dot);
            dot = fmaf(zv.y, cv.y, dot);
            dot = fmaf(zv.z, cv.z, dot);
            dot = fmaf(zv.w, cv.w, dot);
        }
        float d = __fsub_rn(__fadd_rn(sA[q], __ldg(&g_B[cdx])),
                            __fmul_rn(2.0f, dot));
        atomicMin(&best[q],
                  ((unsigned long long)__float_as_uint(d) << 32) | (uint32_t)cdx);
    }
    // rare overflow fallback: full scan for that query by the whole block
    for (int qq = 0; qq < EX_Q; qq++) {
        if (!sovf[qq]) continue;
        const float4* zr = zs + qq * 65;
        const float A = sA[qq];
        for (int cdx = tid; cdx < NE; cdx += 256) {
            const float4* crow = cb4 + (size_t)cdx * 64;
            float dot = 0.0f;
            #pragma unroll 8
            for (int f = 0; f < 64; f++) {
                float4 zv = zr[f];
                float4 cv = __ldg(crow + f);
                dot = fmaf(zv.x, cv.x, dot);
                dot = fmaf(zv.y, cv.y, dot);
                dot = fmaf(zv.z, cv.z, dot);
                dot = fmaf(zv.w, cv.w, dot);
            }
            float d = __fsub_rn(__fadd_rn(A, __ldg(&g_B[cdx])),
                                __fmul_rn(2.0f, dot));
            atomicMin(&best[qq],
                      ((unsigned long long)__float_as_uint(d) << 32) | (uint32_t)cdx);
        }
    }
    __syncthreads();
    if (tid < EX_Q) widx[tid] = (int)(best[tid] & 0xFFFFFFFFull);
    __syncthreads();

    float4* out4 = (float4*)out;
    for (int e = tid; e < EX_Q * 64; e += 256) {
        int r = e >> 6, c = e & 63;
        out4[(size_t)(q0 + r) * 64 + c] = __ldg(cb4 + (size_t)widx[r] * 64 + c);
    }
}

// ---------------------------------------------------------------------------
extern "C" void kernel_launch(void* const* d_in, const int* in_sizes, int n_in,
                              void* d_out, int out_size) {
    const float* z  = (const float*)d_in[0];   // [32,2048,256] f32
    const float* cb = (const float*)d_in[1];   // [4096,256] f32
    float* out = (float*)d_out;

    cudaFuncSetAttribute(vq_screen, cudaFuncAttributeMaxDynamicSharedMemorySize,
                         SCREEN_SMEM);
    cudaFuncSetAttribute(vq_exact, cudaFuncAttributeMaxDynamicSharedMemorySize,
                         EXACT_SMEM);

    rowsq_z  <<<NQ / 256, 256>>>((const float4*)z);
    rowsq_cb <<<NE / 256, 256>>>((const float4*)cb);
    cvt_cb   <<<(NE * ED / 8) / 256, 256>>>((const float4*)cb);
    vq_screen<<<NQ / QB, 288, SCREEN_SMEM>>>(z, cb);
    vq_exact <<<NQ / EX_Q, 256, EXACT_SMEM>>>(z, cb, out);
}

// round 9
// speedup vs baseline: 1.0022x; 1.0022x over previous
#include <cuda_runtime.h>
#include <cuda_bf16.h>
#include <float.h>
#include <stdint.h>

#define NQ    65536
#define NE    4096
#define ED    256
#define CAND  64
#define W_MARGIN 1.0e-3f

#define QB     256          // queries per CTA (screen)
#define TN     64           // codes per tile
#define NTILES (NE / TN)    // 64

// Scratch (no allocations allowed)
__device__ float g_A[NQ];
__device__ float g_B[NE];
__device__ int   g_cnt[NQ];
__device__ int   g_cand[NQ * CAND];
__device__ __nv_bfloat16 g_cbbf[NE * ED];   // bf16 codebook (2MB, L2-resident)

// ---------------------------------------------------------------------------
// helpers (base-ISA only: harness PTX target is sm_103 base — no tcgen05)
// ---------------------------------------------------------------------------
__device__ __forceinline__ uint32_t smem_u32(const void* p) {
    uint32_t a;
    asm("{ .reg .u64 t; cvta.to.shared.u64 t, %1; cvt.u32.u64 %0, t; }"
        : "=r"(a) : "l"(p));
    return a;
}
__device__ __forceinline__ void mbar_init(uint32_t a, uint32_t n) {
    asm volatile("mbarrier.init.shared.b64 [%0], %1;" :: "r"(a), "r"(n) : "memory");
}
__device__ __forceinline__ void mbar_arrive(uint32_t a) {
    asm volatile("mbarrier.arrive.shared.b64 _, [%0];" :: "r"(a) : "memory");
}
__device__ __forceinline__ void mbar_wait(uint32_t a, uint32_t ph) {
    uint32_t done;
    asm volatile("{\n\t.reg .pred p;\n\t"
                 "mbarrier.try_wait.parity.acquire.cta.shared::cta.b64 p, [%1], %2;\n\t"
                 "selp.b32 %0,1,0,p;\n\t}"
                 : "=r"(done) : "r"(a), "r"(ph) : "memory");
    if (!done) {
        asm volatile("{\n\t.reg .pred P1;\n\t"
                     "WL_%=:\n\t"
                     "mbarrier.try_wait.parity.acquire.cta.shared::cta.b64 P1, [%0], %1, 0x989680;\n\t"
                     "@P1 bra.uni WD_%=;\n\t"
                     "bra.uni WL_%=;\n\t"
                     "WD_%=:\n\t}"
                     :: "r"(a), "r"(ph) : "memory");
    }
}
__device__ __forceinline__ void cp16(uint32_t dst, const void* src) {
    asm volatile("cp.async.ca.shared.global [%0], [%1], 16;"
                 :: "r"(dst), "l"(src) : "memory");
}
// pack two f32 -> bf16x2 (rne): lo in low half, hi in high half
__device__ __forceinline__ uint32_t pk2(float lo, float hi) {
    uint32_t r;
    asm("cvt.rn.bf16x2.f32 %0, %1, %2;" : "=r"(r) : "f"(hi), "f"(lo));
    return r;
}
__device__ __forceinline__ void ldsm4(uint32_t r[4], uint32_t addr) {
    asm volatile("ldmatrix.sync.aligned.m8n8.x4.shared.b16 {%0,%1,%2,%3}, [%4];"
                 : "=r"(r[0]), "=r"(r[1]), "=r"(r[2]), "=r"(r[3]) : "r"(addr));
}
__device__ __forceinline__ void mma_bf16(float c[4], const uint32_t a[4],
                                         uint32_t b0, uint32_t b1) {
    asm volatile("mma.sync.aligned.m16n8k16.row.col.f32.bf16.bf16.f32 "
                 "{%0,%1,%2,%3}, {%4,%5,%6,%7}, {%8,%9}, {%0,%1,%2,%3};"
                 : "+f"(c[0]), "+f"(c[1]), "+f"(c[2]), "+f"(c[3])
                 : "r"(a[0]), "r"(a[1]), "r"(a[2]), "r"(a[3]), "r"(b0), "r"(b1));
}

// ---------------------------------------------------------------------------
// Row sums of squares — bit-exact reference order: fadd(fmul), sequential.
// ---------------------------------------------------------------------------
__global__ void rowsq_z(const float4* __restrict__ z4) {
    int n = blockIdx.x * blockDim.x + threadIdx.x;
    if (n >= NQ) return;
    const float4* p = z4 + (size_t)n * (ED / 4);
    float acc = 0.0f;
    #pragma unroll 8
    for (int i = 0; i < ED / 4; i++) {
        float4 v = __ldg(p + i);
        acc = __fadd_rn(acc, __fmul_rn(v.x, v.x));
        acc = __fadd_rn(acc, __fmul_rn(v.y, v.y));
        acc = __fadd_rn(acc, __fmul_rn(v.z, v.z));
        acc = __fadd_rn(acc, __fmul_rn(v.w, v.w));
    }
    g_A[n] = acc;
}

__global__ void rowsq_cb(const float4* __restrict__ c4) {
    int n = blockIdx.x * blockDim.x + threadIdx.x;
    if (n >= NE) return;
    const float4* p = c4 + (size_t)n * (ED / 4);
    float acc = 0.0f;
    #pragma unroll 8
    for (int i = 0; i < ED / 4; i++) {
        float4 v = __ldg(p + i);
        acc = __fadd_rn(acc, __fmul_rn(v.x, v.x));
        acc = __fadd_rn(acc, __fmul_rn(v.y, v.y));
        acc = __fadd_rn(acc, __fmul_rn(v.z, v.z));
        acc = __fadd_rn(acc, __fmul_rn(v.w, v.w));
    }
    g_B[n] = acc;
}

// Codebook f32 -> bf16 (rne), natural element order, coalesced.
__global__ void cvt_cb(const float4* __restrict__ c4) {
    int t = blockIdx.x * 256 + threadIdx.x;   // NE*ED/8 = 131072
    if (t >= NE * ED / 8) return;
    float4 v0 = __ldg(c4 + 2 * t);
    float4 v1 = __ldg(c4 + 2 * t + 1);
    uint4 o;
    o.x = pk2(v0.x, v0.y); o.y = pk2(v0.z, v0.w);
    o.z = pk2(v1.x, v1.y); o.w = pk2(v1.z, v1.w);
    ((uint4*)g_cbbf)[t] = o;
}

// ---------------------------------------------------------------------------
// Phase 1: bf16 mma.sync screening, warp-specialized.
// CTA = 256 queries (A bf16 persistent in smem). 8 consumer warps (32q x 64c
// each); 1 producer warp cp.asyncs the pre-converted bf16 B tile + row-sumsq
// through a 2-deep mbarrier ring. Collects codes with s <= runmin + W.
// ---------------------------------------------------------------------------
#define SA_OFF   0
#define SB_OFF   131072
#define BSQ_OFF  196608
#define CNT_OFF  197120
#define MB_OFF   198144
#define SCREEN_SMEM (198176 + 1024)

__global__ void __launch_bounds__(288, 1)
vq_screen(const float* __restrict__ z, const float* __restrict__ cb) {
    extern __shared__ char smraw[];
    char* smem = (char*)(((uintptr_t)smraw + 1023) & ~(uintptr_t)1023);
    const uint32_t smb = smem_u32(smem);

    const int tid  = threadIdx.x;
    const int lane = tid & 31;
    const int w    = tid >> 5;           // 0..8
    const int q0   = blockIdx.x * QB;

    float* bsq = (float*)(smem + BSQ_OFF);
    int*   cnt = (int*)(smem + CNT_OFF);
    const uint32_t mb = smb + MB_OFF;    // +0/+8 full[2], +16/+24 empty[2]

    const float4* z4 = (const float4*)z;

    if (tid == 0) {
        mbar_init(mb + 0, 32);  mbar_init(mb + 8, 32);    // full: producer warp
        mbar_init(mb + 16, 256); mbar_init(mb + 24, 256); // empty: consumers
    }
    if (tid < 256) cnt[tid] = 0;

    // ---- stage A: f32 -> bf16 (rne), rows of 512B, 16B-unit XOR swizzle ----
    for (int e = tid; e < QB * 32; e += 288) {
        int q = e >> 5, c = e & 31;
        float4 v0 = __ldg(z4 + (size_t)(q0 + q) * 64 + 2 * c);
        float4 v1 = __ldg(z4 + (size_t)(q0 + q) * 64 + 2 * c + 1);
        uint4 t;
        t.x = pk2(v0.x, v0.y); t.y = pk2(v0.z, v0.w);
        t.z = pk2(v1.x, v1.y); t.w = pk2(v1.z, v1.w);
        *(uint4*)(smem + SA_OFF + q * 512 + ((c ^ (q & 7)) << 4)) = t;
    }
    __syncthreads();

    if (w == 8) {
        // ---------------- producer warp: pure cp.async staging ----------------
        const char* src = (const char*)g_cbbf;
        for (int nt = 0; nt < NTILES; nt++) {
            const int b = nt & 1;
            if (nt >= 2) mbar_wait(mb + 16 + b * 8, ((nt - 2) >> 1) & 1);
            const uint32_t bp = smb + SB_OFF + b * 32768;
            const size_t gs = (size_t)nt * TN * 512;   // bytes (bf16 rows=512B)
            #pragma unroll 8
            for (int r = 0; r < TN; r++)
                cp16(bp + r * 512 + (((uint32_t)(lane ^ (r & 7))) << 4),
                     src + gs + r * 512 + lane * 16);
            if (lane < 16)
                cp16(smb + BSQ_OFF + b * 256 + lane * 16,
                     (const char*)g_B + (size_t)nt * 256 + lane * 16);
            asm volatile("cp.async.commit_group;" ::: "memory");
            if (nt >= 1) {
                asm volatile("cp.async.wait_group 1;" ::: "memory");
                mbar_arrive(mb + ((nt - 1) & 1) * 8);
            }
        }
        asm volatile("cp.async.wait_group 0;" ::: "memory");
        mbar_arrive(mb + ((NTILES - 1) & 1) * 8);
    } else {
        // ---------------- consumers (warps 0-7): 32q x 64c each ----------------
        float Aq[4], runmin[4];
        int qloc[4];
        #pragma unroll
        for (int i = 0; i < 4; i++) {
            qloc[i] = w * 32 + i * 8 + (lane >> 2);
            Aq[i] = g_A[q0 + qloc[i]];
            runmin[i] = FLT_MAX;
        }

        for (int nt = 0; nt < NTILES; nt++) {
            const int b = nt & 1;
            mbar_wait(mb + b * 8, (nt >> 1) & 1);

            float acc[2][8][4];
            #pragma unroll
            for (int mi = 0; mi < 2; mi++)
                #pragma unroll
                for (int j = 0; j < 8; j++)
                    #pragma unroll
                    for (int p = 0; p < 4; p++) acc[mi][j][p] = 0.0f;

            const uint32_t sb_base = smb + SB_OFF + b * 32768;
            #pragma unroll
            for (int kc = 0; kc < 16; kc++) {
                uint32_t a[2][4];
                #pragma unroll
                for (int mi = 0; mi < 2; mi++) {
                    int qr = w * 32 + mi * 16 + (lane & 15);
                    uint32_t ad = smb + SA_OFF + qr * 512 +
                        ((((kc << 1) | (lane >> 4)) ^ (qr & 7)) << 4);
                    ldsm4(a[mi], ad);
                }
                uint32_t bf[4][4];
                #pragma unroll
                for (int jp = 0; jp < 4; jp++) {
                    int nr = jp * 16 + (lane & 7) + ((lane & 16) >> 1);
                    int cc = (kc << 1) | ((lane >> 3) & 1);
                    uint32_t ad = sb_base + nr * 512 + ((cc ^ (nr & 7)) << 4);
                    ldsm4(bf[jp], ad);
                }
                #pragma unroll
                for (int mi = 0; mi < 2; mi++)
                    #pragma unroll
                    for (int jp = 0; jp < 4; jp++) {
                        mma_bf16(acc[mi][jp * 2],     a[mi], bf[jp][0], bf[jp][1]);
                        mma_bf16(acc[mi][jp * 2 + 1], a[mi], bf[jp][2], bf[jp][3]);
                    }
            }

            float Bn[16];
            #pragma unroll
            for (int j = 0; j < 8; j++) {
                Bn[2 * j]     = bsq[b * 64 + j * 8 + (lane & 3) * 2];
                Bn[2 * j + 1] = bsq[b * 64 + j * 8 + (lane & 3) * 2 + 1];
            }
            mbar_arrive(mb + 16 + b * 8);

            const int n0t = nt * TN;
            float thr[4];
            #pragma unroll
            for (int i = 0; i < 4; i++) {
                const int mi = i >> 1, rh = i & 1;
                float m = FLT_MAX;
                #pragma unroll
                for (int j = 0; j < 8; j++) {
                    float v0 = fmaf(-2.0f, acc[mi][j][rh * 2],     Aq[i] + Bn[2 * j]);
                    float v1 = fmaf(-2.0f, acc[mi][j][rh * 2 + 1], Aq[i] + Bn[2 * j + 1]);
                    m = fminf(m, fminf(v0, v1));
                }
                m = fminf(m, __shfl_xor_sync(~0u, m, 1));
                m = fminf(m, __shfl_xor_sync(~0u, m, 2));
                runmin[i] = fminf(runmin[i], m);
                thr[i] = runmin[i] + W_MARGIN;
            }
            #pragma unroll
            for (int i = 0; i < 4; i++) {
                const int mi = i >> 1, rh = i & 1;
                #pragma unroll
                for (int j = 0; j < 8; j++) {
                    #pragma unroll
                    for (int p = 0; p < 2; p++) {
                        float v = fmaf(-2.0f, acc[mi][j][rh * 2 + p],
                                       Aq[i] + Bn[2 * j + p]);
                        if (v <= thr[i]) {
                            int sl = atomicAdd(&cnt[qloc[i]], 1);
                            if (sl < CAND)
                                g_cand[(size_t)(q0 + qloc[i]) * CAND + sl] =
                                    n0t + j * 8 + (lane & 3) * 2 + p;
                        }
                    }
                }
            }
        }
    }

    __syncthreads();
    if (tid < 256) g_cnt[q0 + tid] = cnt[tid];
}

// ---------------------------------------------------------------------------
// Phase 2: exact verification, 64 queries per block. z rows staged in smem
// (padded, conflict-free); (q,cand) pairs flattened into a work queue so all
// lanes stay busy; winner = packed-u64 atomicMin (d>0 => float bits monotone;
// low word = idx => exact first-index tie-break). Overflow -> full scan.
// ---------------------------------------------------------------------------
#define EX_Q 64
#define XS_Z    0                    // 64 rows x 65 float4 = 66560B
#define XS_PAIR 66560                // 4096 x u32 = 16384
#define XS_BEST 82944                // 64 x u64 = 512
#define XS_A    83456                // 64 x f32
#define XS_CNT  83712                // 64 x i32
#define XS_PREF 83968                // 65 x i32 (+pad)
#define XS_OVF  84240                // 64 x i32
#define XS_WIDX 84496                // 64 x i32
#define EXACT_SMEM 84752

__global__ void __launch_bounds__(256, 2)
vq_exact(const float* __restrict__ z, const float* __restrict__ cb,
         float* __restrict__ out) {
    extern __shared__ char sm[];
    float4*             zs    = (float4*)(sm + XS_Z);
    uint32_t*           pairs = (uint32_t*)(sm + XS_PAIR);
    unsigned long long* best  = (unsigned long long*)(sm + XS_BEST);
    float*              sA    = (float*)(sm + XS_A);
    int*                scnt  = (int*)(sm + XS_CNT);
    int*                spref = (int*)(sm + XS_PREF);
    int*                sovf  = (int*)(sm + XS_OVF);
    int*                widx  = (int*)(sm + XS_WIDX);

    const int tid = threadIdx.x;
    const int q0  = blockIdx.x * EX_Q;

    const float4* z4  = (const float4*)z;
    const float4* cb4 = (const float4*)cb;

    if (tid < EX_Q) {
        int c = g_cnt[q0 + tid];
        int ov = (c > CAND);
        sovf[tid] = ov;
        scnt[tid] = ov ? 0 : c;
        sA[tid]   = g_A[q0 + tid];
        best[tid] = 0xFFFFFFFFFFFFFFFFull;
    }
    for (int e = tid; e < EX_Q * 64; e += 256) {
        int r = e >> 6, f = e & 63;
        zs[r * 65 + f] = __ldg(z4 + (size_t)(q0 + r) * 64 + f);
    }
    __syncthreads();
    if (tid == 0) {
        int run = 0;
        for (int i = 0; i < EX_Q; i++) { spref[i] = run; run += scnt[i]; }
        spref[EX_Q] = run;
    }
    __syncthreads();
    if (tid < EX_Q) {
        int p0 = spref[tid], n = scnt[tid];
        for (int j = 0; j < n; j++)
            pairs[p0 + j] = ((uint32_t)tid << 12)
                          | (uint32_t)g_cand[(size_t)(q0 + tid) * CAND + j];
    }
    __syncthreads();

    const int total = spref[EX_Q];
    for (int p = tid; p < total; p += 256) {
        uint32_t pr = pairs[p];
        int q = pr >> 12, cdx = pr & 4095;
        const float4* crow = cb4 + (size_t)cdx * 64;
        const float4* zr = zs + q * 65;
        float dot = 0.0f;
        #pragma unroll 8
        for (int f = 0; f < 64; f++) {
            float4 zv = zr[f];
            float4 cv = __ldg(crow + f);
            dot = fmaf(zv.x, cv.x, dot);
            dot = fmaf(zv.y, cv.y, dot);
            dot = fmaf(zv.z, cv.z, dot);
            dot = fmaf(zv.w, cv.w, dot);
        }
        float d = __fsub_rn(__fadd_rn(sA[q], __ldg(&g_B[cdx])),
                            __fmul_rn(2.0f, dot));
        atomicMin(&best[q],
                  ((unsigned long long)__float_as_uint(d) << 32) | (uint32_t)cdx);
    }
    // rare overflow fallback: full scan for that query by the whole block
    for (int qq = 0; qq < EX_Q; qq++) {
        if (!sovf[qq]) continue;
        const float4* zr = zs + qq * 65;
        const float A = sA[qq];
        for (int cdx = tid; cdx < NE; cdx += 256) {
            const float4* crow = cb4 + (size_t)cdx * 64;
            float dot = 0.0f;
            #pragma unroll 8
            for (int f = 0; f < 64; f++) {
                float4 zv = zr[f];
                float4 cv = __ldg(crow + f);
                dot = fmaf(zv.x, cv.x, dot);
                dot = fmaf(zv.y, cv.y, dot);
                dot = fmaf(zv.z, cv.z, dot);
                dot = fmaf(zv.w, cv.w, dot);
            }
            float d = __fsub_rn(__fadd_rn(A, __ldg(&g_B[cdx])),
                                __fmul_rn(2.0f, dot));
            atomicMin(&best[qq],
                      ((unsigned long long)__float_as_uint(d) << 32) | (uint32_t)cdx);
        }
    }
    __syncthreads();
    if (tid < EX_Q) widx[tid] = (int)(best[tid] & 0xFFFFFFFFull);
    __syncthreads();

    float4* out4 = (float4*)out;
    for (int e = tid; e < EX_Q * 64; e += 256) {
        int r = e >> 6, c = e & 63;
        out4[(size_t)(q0 + r) * 64 + c] = __ldg(cb4 + (size_t)widx[r] * 64 + c);
    }
}

// ---------------------------------------------------------------------------
extern "C" void kernel_launch(void* const* d_in, const int* in_sizes, int n_in,
                              void* d_out, int out_size) {
    const float* z  = (const float*)d_in[0];   // [32,2048,256] f32
    const float* cb = (const float*)d_in[1];   // [4096,256] f32
    float* out = (float*)d_out;

    cudaFuncSetAttribute(vq_screen, cudaFuncAttributeMaxDynamicSharedMemorySize,
                         SCREEN_SMEM);
    cudaFuncSetAttribute(vq_exact, cudaFuncAttributeMaxDynamicSharedMemorySize,
                         EXACT_SMEM);

    rowsq_z  <<<NQ / 256, 256>>>((const float4*)z);
    rowsq_cb <<<NE / 256, 256>>>((const float4*)cb);
    cvt_cb   <<<(NE * ED / 8) / 256, 256>>>((const float4*)cb);
    vq_screen<<<NQ / QB, 288, SCREEN_SMEM>>>(z, cb);
    vq_exact <<<NQ / EX_Q, 256, EXACT_SMEM>>>(z, cb, out);
}

// round 10
// speedup vs baseline: 1.0045x; 1.0023x over previous
#include <cuda_runtime.h>
#include <cuda_bf16.h>
#include <float.h>
#include <stdint.h>

#define NQ    65536
#define NE    4096
#define ED    256
#define CAND  64
#define W_MARGIN 1.0e-3f

#define QB     256          // queries per CTA (screen)
#define TN     64           // codes per tile
#define NTILES (NE / TN)    // 64

// Scratch (no allocations allowed)
__device__ float g_A[NQ];
__device__ float g_B[NE];
__device__ int   g_cnt[NQ];
__device__ int   g_cand[NQ * CAND];
__device__ __nv_bfloat16 g_cbbf[NE * ED];   // bf16 codebook (2MB, L2-resident)

// ---------------------------------------------------------------------------
// helpers (base-ISA only: harness PTX target is sm_103 base — no tcgen05)
// ---------------------------------------------------------------------------
__device__ __forceinline__ uint32_t smem_u32(const void* p) {
    uint32_t a;
    asm("{ .reg .u64 t; cvta.to.shared.u64 t, %1; cvt.u32.u64 %0, t; }"
        : "=r"(a) : "l"(p));
    return a;
}
__device__ __forceinline__ void mbar_init(uint32_t a, uint32_t n) {
    asm volatile("mbarrier.init.shared.b64 [%0], %1;" :: "r"(a), "r"(n) : "memory");
}
__device__ __forceinline__ void mbar_arrive(uint32_t a) {
    asm volatile("mbarrier.arrive.shared.b64 _, [%0];" :: "r"(a) : "memory");
}
__device__ __forceinline__ void mbar_wait(uint32_t a, uint32_t ph) {
    uint32_t done;
    asm volatile("{\n\t.reg .pred p;\n\t"
                 "mbarrier.try_wait.parity.acquire.cta.shared::cta.b64 p, [%1], %2;\n\t"
                 "selp.b32 %0,1,0,p;\n\t}"
                 : "=r"(done) : "r"(a), "r"(ph) : "memory");
    if (!done) {
        asm volatile("{\n\t.reg .pred P1;\n\t"
                     "WL_%=:\n\t"
                     "mbarrier.try_wait.parity.acquire.cta.shared::cta.b64 P1, [%0], %1, 0x989680;\n\t"
                     "@P1 bra.uni WD_%=;\n\t"
                     "bra.uni WL_%=;\n\t"
                     "WD_%=:\n\t}"
                     :: "r"(a), "r"(ph) : "memory");
    }
}
__device__ __forceinline__ void cp16(uint32_t dst, const void* src) {
    asm volatile("cp.async.ca.shared.global [%0], [%1], 16;"
                 :: "r"(dst), "l"(src) : "memory");
}
// pack two f32 -> bf16x2 (rne): lo in low half, hi in high half
__device__ __forceinline__ uint32_t pk2(float lo, float hi) {
    uint32_t r;
    asm("cvt.rn.bf16x2.f32 %0, %1, %2;" : "=r"(r) : "f"(hi), "f"(lo));
    return r;
}
__device__ __forceinline__ void ldsm4(uint32_t r[4], uint32_t addr) {
    asm volatile("ldmatrix.sync.aligned.m8n8.x4.shared.b16 {%0,%1,%2,%3}, [%4];"
                 : "=r"(r[0]), "=r"(r[1]), "=r"(r[2]), "=r"(r[3]) : "r"(addr));
}
__device__ __forceinline__ void mma_bf16(float c[4], const uint32_t a[4],
                                         uint32_t b0, uint32_t b1) {
    asm volatile("mma.sync.aligned.m16n8k16.row.col.f32.bf16.bf16.f32 "
                 "{%0,%1,%2,%3}, {%4,%5,%6,%7}, {%8,%9}, {%0,%1,%2,%3};"
                 : "+f"(c[0]), "+f"(c[1]), "+f"(c[2]), "+f"(c[3])
                 : "r"(a[0]), "r"(a[1]), "r"(a[2]), "r"(a[3]), "r"(b0), "r"(b1));
}

// ---------------------------------------------------------------------------
// Row sums of squares — bit-exact reference order: fadd(fmul), sequential.
// ---------------------------------------------------------------------------
__global__ void rowsq_z(const float4* __restrict__ z4) {
    int n = blockIdx.x * blockDim.x + threadIdx.x;
    if (n >= NQ) return;
    const float4* p = z4 + (size_t)n * (ED / 4);
    float acc = 0.0f;
    #pragma unroll 8
    for (int i = 0; i < ED / 4; i++) {
        float4 v = __ldg(p + i);
        acc = __fadd_rn(acc, __fmul_rn(v.x, v.x));
        acc = __fadd_rn(acc, __fmul_rn(v.y, v.y));
        acc = __fadd_rn(acc, __fmul_rn(v.z, v.z));
        acc = __fadd_rn(acc, __fmul_rn(v.w, v.w));
    }
    g_A[n] = acc;
}

__global__ void rowsq_cb(const float4* __restrict__ c4) {
    int n = blockIdx.x * blockDim.x + threadIdx.x;
    if (n >= NE) return;
    const float4* p = c4 + (size_t)n * (ED / 4);
    float acc = 0.0f;
    #pragma unroll 8
    for (int i = 0; i < ED / 4; i++) {
        float4 v = __ldg(p + i);
        acc = __fadd_rn(acc, __fmul_rn(v.x, v.x));
        acc = __fadd_rn(acc, __fmul_rn(v.y, v.y));
        acc = __fadd_rn(acc, __fmul_rn(v.z, v.z));
        acc = __fadd_rn(acc, __fmul_rn(v.w, v.w));
    }
    g_B[n] = acc;
}

// Codebook f32 -> bf16 (rne), natural element order, coalesced.
__global__ void cvt_cb(const float4* __restrict__ c4) {
    int t = blockIdx.x * 256 + threadIdx.x;   // NE*ED/8 = 131072
    if (t >= NE * ED / 8) return;
    float4 v0 = __ldg(c4 + 2 * t);
    float4 v1 = __ldg(c4 + 2 * t + 1);
    uint4 o;
    o.x = pk2(v0.x, v0.y); o.y = pk2(v0.z, v0.w);
    o.z = pk2(v1.x, v1.y); o.w = pk2(v1.z, v1.w);
    ((uint4*)g_cbbf)[t] = o;
}

// ---------------------------------------------------------------------------
// Phase 1: bf16 mma.sync screening, warp-specialized.
// CTA = 256 queries (A bf16 persistent in smem). 8 consumer warps (32q x 64c
// each); 1 producer warp cp.asyncs the pre-converted bf16 B tile + row-sumsq
// through a 2-deep mbarrier ring. Collects codes with s <= runmin + W.
// ---------------------------------------------------------------------------
#define SA_OFF   0
#define SB_OFF   131072
#define BSQ_OFF  196608
#define CNT_OFF  197120
#define MB_OFF   198144
#define SCREEN_SMEM (198176 + 1024)

__global__ void __launch_bounds__(288, 1)
vq_screen(const float* __restrict__ z, const float* __restrict__ cb) {
    extern __shared__ char smraw[];
    char* smem = (char*)(((uintptr_t)smraw + 1023) & ~(uintptr_t)1023);
    const uint32_t smb = smem_u32(smem);

    const int tid  = threadIdx.x;
    const int lane = tid & 31;
    const int w    = tid >> 5;           // 0..8
    const int q0   = blockIdx.x * QB;

    float* bsq = (float*)(smem + BSQ_OFF);
    int*   cnt = (int*)(smem + CNT_OFF);
    const uint32_t mb = smb + MB_OFF;    // +0/+8 full[2], +16/+24 empty[2]

    const float4* z4 = (const float4*)z;

    if (tid == 0) {
        mbar_init(mb + 0, 32);  mbar_init(mb + 8, 32);    // full: producer warp
        mbar_init(mb + 16, 256); mbar_init(mb + 24, 256); // empty: consumers
    }
    if (tid < 256) cnt[tid] = 0;

    // ---- stage A: f32 -> bf16 (rne), rows of 512B, 16B-unit XOR swizzle ----
    for (int e = tid; e < QB * 32; e += 288) {
        int q = e >> 5, c = e & 31;
        float4 v0 = __ldg(z4 + (size_t)(q0 + q) * 64 + 2 * c);
        float4 v1 = __ldg(z4 + (size_t)(q0 + q) * 64 + 2 * c + 1);
        uint4 t;
        t.x = pk2(v0.x, v0.y); t.y = pk2(v0.z, v0.w);
        t.z = pk2(v1.x, v1.y); t.w = pk2(v1.z, v1.w);
        *(uint4*)(smem + SA_OFF + q * 512 + ((c ^ (q & 7)) << 4)) = t;
    }
    __syncthreads();

    if (w == 8) {
        // ---------------- producer warp: pure cp.async staging ----------------
        const char* src = (const char*)g_cbbf;
        for (int nt = 0; nt < NTILES; nt++) {
            const int b = nt & 1;
            if (nt >= 2) mbar_wait(mb + 16 + b * 8, ((nt - 2) >> 1) & 1);
            const uint32_t bp = smb + SB_OFF + b * 32768;
            const size_t gs = (size_t)nt * TN * 512;   // bytes (bf16 rows=512B)
            #pragma unroll 8
            for (int r = 0; r < TN; r++)
                cp16(bp + r * 512 + (((uint32_t)(lane ^ (r & 7))) << 4),
                     src + gs + r * 512 + lane * 16);
            if (lane < 16)
                cp16(smb + BSQ_OFF + b * 256 + lane * 16,
                     (const char*)g_B + (size_t)nt * 256 + lane * 16);
            asm volatile("cp.async.commit_group;" ::: "memory");
            if (nt >= 1) {
                asm volatile("cp.async.wait_group 1;" ::: "memory");
                mbar_arrive(mb + ((nt - 1) & 1) * 8);
            }
        }
        asm volatile("cp.async.wait_group 0;" ::: "memory");
        mbar_arrive(mb + ((NTILES - 1) & 1) * 8);
    } else {
        // ---------------- consumers (warps 0-7): 32q x 64c each ----------------
        float Aq[4], runmin[4];
        int qloc[4];
        #pragma unroll
        for (int i = 0; i < 4; i++) {
            qloc[i] = w * 32 + i * 8 + (lane >> 2);
            Aq[i] = g_A[q0 + qloc[i]];
            runmin[i] = FLT_MAX;
        }

        for (int nt = 0; nt < NTILES; nt++) {
            const int b = nt & 1;
            mbar_wait(mb + b * 8, (nt >> 1) & 1);

            float acc[2][8][4];
            #pragma unroll
            for (int mi = 0; mi < 2; mi++)
                #pragma unroll
                for (int j = 0; j < 8; j++)
                    #pragma unroll
                    for (int p = 0; p < 4; p++) acc[mi][j][p] = 0.0f;

            const uint32_t sb_base = smb + SB_OFF + b * 32768;
            #pragma unroll
            for (int kc = 0; kc < 16; kc++) {
                uint32_t a[2][4];
                #pragma unroll
                for (int mi = 0; mi < 2; mi++) {
                    int qr = w * 32 + mi * 16 + (lane & 15);
                    uint32_t ad = smb + SA_OFF + qr * 512 +
                        ((((kc << 1) | (lane >> 4)) ^ (qr & 7)) << 4);
                    ldsm4(a[mi], ad);
                }
                uint32_t bf[4][4];
                #pragma unroll
                for (int jp = 0; jp < 4; jp++) {
                    int nr = jp * 16 + (lane & 7) + ((lane & 16) >> 1);
                    int cc = (kc << 1) | ((lane >> 3) & 1);
                    uint32_t ad = sb_base + nr * 512 + ((cc ^ (nr & 7)) << 4);
                    ldsm4(bf[jp], ad);
                }
                #pragma unroll
                for (int mi = 0; mi < 2; mi++)
                    #pragma unroll
                    for (int jp = 0; jp < 4; jp++) {
                        mma_bf16(acc[mi][jp * 2],     a[mi], bf[jp][0], bf[jp][1]);
                        mma_bf16(acc[mi][jp * 2 + 1], a[mi], bf[jp][2], bf[jp][3]);
                    }
            }

            float Bn[16];
            #pragma unroll
            for (int j = 0; j < 8; j++) {
                Bn[2 * j]     = bsq[b * 64 + j * 8 + (lane & 3) * 2];
                Bn[2 * j + 1] = bsq[b * 64 + j * 8 + (lane & 3) * 2 + 1];
            }
            mbar_arrive(mb + 16 + b * 8);

            const int n0t = nt * TN;
            float thr[4];
            #pragma unroll
            for (int i = 0; i < 4; i++) {
                const int mi = i >> 1, rh = i & 1;
                float m = FLT_MAX;
                #pragma unroll
                for (int j = 0; j < 8; j++) {
                    float v0 = fmaf(-2.0f, acc[mi][j][rh * 2],     Aq[i] + Bn[2 * j]);
                    float v1 = fmaf(-2.0f, acc[mi][j][rh * 2 + 1], Aq[i] + Bn[2 * j + 1]);
                    m = fminf(m, fminf(v0, v1));
                }
                m = fminf(m, __shfl_xor_sync(~0u, m, 1));
                m = fminf(m, __shfl_xor_sync(~0u, m, 2));
                runmin[i] = fminf(runmin[i], m);
                thr[i] = runmin[i] + W_MARGIN;
            }
            #pragma unroll
            for (int i = 0; i < 4; i++) {
                const int mi = i >> 1, rh = i & 1;
                #pragma unroll
                for (int j = 0; j < 8; j++) {
                    #pragma unroll
                    for (int p = 0; p < 2; p++) {
                        float v = fmaf(-2.0f, acc[mi][j][rh * 2 + p],
                                       Aq[i] + Bn[2 * j + p]);
                        if (v <= thr[i]) {
                            int sl = atomicAdd(&cnt[qloc[i]], 1);
                            if (sl < CAND)
                                g_cand[(size_t)(q0 + qloc[i]) * CAND + sl] =
                                    n0t + j * 8 + (lane & 3) * 2 + p;
                        }
                    }
                }
            }
        }
    }

    __syncthreads();
    if (tid < 256) g_cnt[q0 + tid] = cnt[tid];
}

// ---------------------------------------------------------------------------
// Phase 2: exact verification, 64 queries per block. z rows staged in smem
// (padded, conflict-free); (q,cand) pairs flattened into a work queue so all
// lanes stay busy; winner = packed-u64 atomicMin (d>0 => float bits monotone;
// low word = idx => exact first-index tie-break). Overflow -> full scan.
// ---------------------------------------------------------------------------
#define EX_Q 64
#define XS_Z    0                    // 64 rows x 65 float4 = 66560B
#define XS_PAIR 66560                // 4096 x u32 = 16384
#define XS_BEST 82944                // 64 x u64 = 512
#define XS_A    83456                // 64 x f32
#define XS_CNT  83712                // 64 x i32
#define XS_PREF 83968                // 65 x i32 (+pad)
#define XS_OVF  84240                // 64 x i32
#define XS_WIDX 84496                // 64 x i32
#define EXACT_SMEM 84752

__global__ void __launch_bounds__(256, 2)
vq_exact(const float* __restrict__ z, const float* __restrict__ cb,
         float* __restrict__ out) {
    extern __shared__ char sm[];
    float4*             zs    = (float4*)(sm + XS_Z);
    uint32_t*           pairs = (uint32_t*)(sm + XS_PAIR);
    unsigned long long* best  = (unsigned long long*)(sm + XS_BEST);
    float*              sA    = (float*)(sm + XS_A);
    int*                scnt  = (int*)(sm + XS_CNT);
    int*                spref = (int*)(sm + XS_PREF);
    int*                sovf  = (int*)(sm + XS_OVF);
    int*                widx  = (int*)(sm + XS_WIDX);

    const int tid = threadIdx.x;
    const int q0  = blockIdx.x * EX_Q;

    const float4* z4  = (const float4*)z;
    const float4* cb4 = (const float4*)cb;

    if (tid < EX_Q) {
        int c = g_cnt[q0 + tid];
        int ov = (c > CAND);
        sovf[tid] = ov;
        scnt[tid] = ov ? 0 : c;
        sA[tid]   = g_A[q0 + tid];
        best[tid] = 0xFFFFFFFFFFFFFFFFull;
    }
    for (int e = tid; e < EX_Q * 64; e += 256) {
        int r = e >> 6, f = e & 63;
        zs[r * 65 + f] = __ldg(z4 + (size_t)(q0 + r) * 64 + f);
    }
    __syncthreads();
    if (tid == 0) {
        int run = 0;
        for (int i = 0; i < EX_Q; i++) { spref[i] = run; run += scnt[i]; }
        spref[EX_Q] = run;
    }
    __syncthreads();
    if (tid < EX_Q) {
        int p0 = spref[tid], n = scnt[tid];
        for (int j = 0; j < n; j++)
            pairs[p0 + j] = ((uint32_t)tid << 12)
                          | (uint32_t)g_cand[(size_t)(q0 + tid) * CAND + j];
    }
    __syncthreads();

    const int total = spref[EX_Q];
    for (int p = tid; p < total; p += 256) {
        uint32_t pr = pairs[p];
        int q = pr >> 12, cdx = pr & 4095;
        const float4* crow = cb4 + (size_t)cdx * 64;
        const float4* zr = zs + q * 65;
        float dot = 0.0f;
        #pragma unroll 8
        for (int f = 0; f < 64; f++) {
            float4 zv = zr[f];
            float4 cv = __ldg(crow + f);
            dot = fmaf(zv.x, cv.x, dot);
            dot = fmaf(zv.y, cv.y, dot);
            dot = fmaf(zv.z, cv.z, dot);
            dot = fmaf(zv.w, cv.w, dot);
        }
        float d = __fsub_rn(__fadd_rn(sA[q], __ldg(&g_B[cdx])),
                            __fmul_rn(2.0f, dot));
        atomicMin(&best[q],
                  ((unsigned long long)__float_as_uint(d) << 32) | (uint32_t)cdx);
    }
    // rare overflow fallback: full scan for that query by the whole block
    for (int qq = 0; qq < EX_Q; qq++) {
        if (!sovf[qq]) continue;
        const float4* zr = zs + qq * 65;
        const float A = sA[qq];
        for (int cdx = tid; cdx < NE; cdx += 256) {
            const float4* crow = cb4 + (size_t)cdx * 64;
            float dot = 0.0f;
            #pragma unroll 8
            for (int f = 0; f < 64; f++) {
                float4 zv = zr[f];
                float4 cv = __ldg(crow + f);
                dot = fmaf(zv.x, cv.x, dot);
                dot = fmaf(zv.y, cv.y, dot);
                dot = fmaf(zv.z, cv.z, dot);
                dot = fmaf(zv.w, cv.w, dot);
            }
            float d = __fsub_rn(__fadd_rn(A, __ldg(&g_B[cdx])),
                                __fmul_rn(2.0f, dot));
            atomicMin(&best[qq],
                      ((unsigned long long)__float_as_uint(d) << 32) | (uint32_t)cdx);
        }
    }
    __syncthreads();
    if (tid < EX_Q) widx[tid] = (int)(best[tid] & 0xFFFFFFFFull);
    __syncthreads();

    float4* out4 = (float4*)out;
    for (int e = tid; e < EX_Q * 64; e += 256) {
        int r = e >> 6, c = e & 63;
        out4[(size_t)(q0 + r) * 64 + c] = __ldg(cb4 + (size_t)widx[r] * 64 + c);
    }
}

// ---------------------------------------------------------------------------
extern "C" void kernel_launch(void* const* d_in, const int* in_sizes, int n_in,
                              void* d_out, int out_size) {
    const float* z  = (const float*)d_in[0];   // [32,2048,256] f32
    const float* cb = (const float*)d_in[1];   // [4096,256] f32
    float* out = (float*)d_out;

    cudaFuncSetAttribute(vq_screen, cudaFuncAttributeMaxDynamicSharedMemorySize,
                         SCREEN_SMEM);
    cudaFuncSetAttribute(vq_exact, cudaFuncAttributeMaxDynamicSharedMemorySize,
                         EXACT_SMEM);

    rowsq_z  <<<NQ / 256, 256>>>((const float4*)z);
    rowsq_cb <<<NE / 256, 256>>>((const float4*)cb);
    cvt_cb   <<<(NE * ED / 8) / 256, 256>>>((const float4*)cb);
    vq_screen<<<NQ / QB, 288, SCREEN_SMEM>>>(z, cb);
    vq_exact <<<NQ / EX_Q, 256, EXACT_SMEM>>>(z, cb, out);
}